// round 16
// baseline (speedup 1.0000x reference)
#include <cuda_runtime.h>
#include <cuda_fp16.h>
#include <cstdint>

// ---------------------------------------------------------------------------
// Problem constants
// ---------------------------------------------------------------------------
#define NB    32
#define IMGW  224
#define HPIX  (IMGW*IMGW)
#define ED    96
#define KDIM  1200               // 3 * 25 * 16, reordered: k = (rr*16+aa)*3 + c
#define BK    48                 // K-tile = one rr (16 aa x 3 ch); 1200 = 25*48
#define NKT   25
#define MDIM  (NB*16*64)         // 32768 output patches
#define PI_F  3.14159265358979323846f
#define PADH  56                 // smem row pitch in halves (48+8)

#define NSLICE 5                 // fold k-slices per c2
#define NFOLD  (96*NSLICE)       // fold blocks = 480
#define NG4    (NB*HPIX/4)       // 4-pixel repack groups
#define NRB4   (NG4/256)         // repack blocks = 1568

// Scratch (device globals)
__device__ uint4  g_xv[(size_t)NB * HPIX];    // vertical-pair packed image
__device__ __half g_Wt[(size_t)ED * KDIM];    // folded weight [c2][k], reordered k
__device__ float  g_beff[ED];                 // folded bias

// ---------------------------------------------------------------------------
// PTX helpers
// ---------------------------------------------------------------------------
__device__ __forceinline__ void mma_f16(float* c, uint32_t a0, uint32_t a1,
                                        uint32_t a2, uint32_t a3,
                                        uint32_t b0, uint32_t b1) {
    asm volatile(
        "mma.sync.aligned.m16n8k16.row.col.f32.f16.f16.f32 "
        "{%0,%1,%2,%3}, {%4,%5,%6,%7}, {%8,%9}, {%0,%1,%2,%3};"
        : "+f"(c[0]), "+f"(c[1]), "+f"(c[2]), "+f"(c[3])
        : "r"(a0), "r"(a1), "r"(a2), "r"(a3), "r"(b0), "r"(b1));
}
__device__ __forceinline__ uint32_t smem_u32(const void* p) {
    uint32_t a;
    asm("{ .reg .u64 t; cvta.to.shared.u64 t, %1; cvt.u32.u64 %0, t; }" : "=r"(a) : "l"(p));
    return a;
}
__device__ __forceinline__ void cp16(uint32_t dst, const void* src) {
    asm volatile("cp.async.ca.shared.global [%0], [%1], 16;" :: "r"(dst), "l"(src));
}
#define CP_COMMIT()  asm volatile("cp.async.commit_group;" ::: "memory")
#define CP_WAIT(n)   asm volatile("cp.async.wait_group %0;" :: "n"(n) : "memory")
#define LDSM_X4(r0, r1, r2, r3, addr)                                             \
    asm volatile("ldmatrix.sync.aligned.m8n8.x4.shared.b16 {%0,%1,%2,%3}, [%4];"  \
        : "=r"(r0), "=r"(r1), "=r"(r2), "=r"(r3) : "r"(addr))

// ---------------------------------------------------------------------------
// Prep: weight fold (REORDERED k) + 4-pixel repack. Fold blocks first.
// k = (rr*16 + aa)*3 + c  (channels of one grid point adjacent)
// ---------------------------------------------------------------------------
__global__ __launch_bounds__(256)
void prep_repack(const float* __restrict__ x,
                 const float* __restrict__ w1, const float* __restrict__ w2,
                 const float* __restrict__ b1, const float* __restrict__ b2,
                 uint4* __restrict__ xv, __half* __restrict__ Wt,
                 float* __restrict__ beff,
                 float* __restrict__ outTheta, int nTheta) {
    __shared__ float sw2[96*20];
    __shared__ float sw1[96*60];
    __shared__ float red[96];
    int t = threadIdx.x;

    if (blockIdx.x >= NFOLD) {
        // ---- vectorized repack: 4 consecutive pixels (same row) ----
        int g = (blockIdx.x - NFOLD) * 256 + t;
        int b   = g / (HPIX/4);
        int rem = g - b*(HPIX/4);
        int p   = rem * 4;
        int y   = p / IMGW;
        const float* xb = x + (size_t)b*3*HPIX + p;

        float4 f0 = *(const float4*)(xb);
        float4 f1 = *(const float4*)(xb + HPIX);
        float4 f2 = *(const float4*)(xb + 2*HPIX);
        float4 e0 = {0,0,0,0}, e1 = {0,0,0,0}, e2 = {0,0,0,0};
        if (y < IMGW - 1) {
            e0 = *(const float4*)(xb + IMGW);
            e1 = *(const float4*)(xb + HPIX + IMGW);
            e2 = *(const float4*)(xb + 2*HPIX + IMGW);
        }

        uint4* dst = xv + (size_t)b*HPIX + p;
        const float* a0 = &f0.x; const float* a1 = &f1.x; const float* a2 = &f2.x;
        const float* d0 = &e0.x; const float* d1 = &e1.x; const float* d2 = &e2.x;
#pragma unroll
        for (int i = 0; i < 4; i++) {
            __half2 h0 = __floats2half2_rn(a0[i], a1[i]);
            __half2 h1 = __floats2half2_rn(a2[i], 0.f);
            __half2 h2 = __floats2half2_rn(d0[i], d1[i]);
            __half2 h3 = __floats2half2_rn(d2[i], 0.f);
            uint4 v;
            v.x = *reinterpret_cast<uint32_t*>(&h0);
            v.y = *reinterpret_cast<uint32_t*>(&h1);
            v.z = *reinterpret_cast<uint32_t*>(&h2);
            v.w = *reinterpret_cast<uint32_t*>(&h3);
            dst[i] = v;
        }
        return;
    }

    // ---- weight fold: c2 = blk/NSLICE, k = slice*256 + t, REORDERED decode ----
    int c2    = blockIdx.x / NSLICE;
    int slice = blockIdx.x - c2*NSLICE;

    for (int i = t; i < 96*20; i += 256) sw2[i] = w2[(size_t)c2*1920 + i];
    for (int i = t; i < 96*60; i += 256) sw1[i] = w1[i];
    __syncthreads();

    int k = slice*256 + t;
    if (k < KDIM) {
        int gidx = k / 3;
        int c    = k - gidx*3;
        int rr = gidx >> 4, aa = gidx & 15;
        int i = rr / 5, p = rr - i*5;
        int j = aa >> 2, q = aa & 3;
        int o2 = i*4 + j;
        int o1 = c*20 + p*4 + q;
        float s = 0.f;
#pragma unroll 8
        for (int c1 = 0; c1 < 96; c1++)
            s += sw2[c1*20 + o2] * sw1[c1*60 + o1];
        Wt[(size_t)c2*KDIM + k] = __float2half_rn(s);
    }

    if (slice == 0) {
        if (t < 96) {
            float s = 0.f;
#pragma unroll
            for (int e = 0; e < 20; e++) s += sw2[t*20 + e];
            red[t] = s * b1[t];
        }
        __syncthreads();
        if (t == 0) {
            float s = b2[c2];
#pragma unroll 8
            for (int i = 0; i < 96; i++) s += red[i];
            beff[c2] = s;
        }
        if (c2 == 0 && t < nTheta) outTheta[t] = 1.5707963267948966f;   // pi/2
    }
}

// ---------------------------------------------------------------------------
// FUSED sample + GEMM. One CTA = 128 patches (one batch, 2 radius groups).
// K-tile kt == radius row rr: sample 2 azimuth rings (pr0, pr0+1) directly
// into As smem (k-local = 3*aa + c), cp.async the 48-col B slice, then MMA.
// ---------------------------------------------------------------------------
#define ASZ (128*PADH)           // 7168 halves = 14336 B
#define BSZ (96*PADH)            // 5376 halves = 10752 B

__global__ __launch_bounds__(256)
void fused_gemm(const uint4* __restrict__ xv, const float* __restrict__ dist,
                const __half* __restrict__ Bw, const float* __restrict__ bias,
                float* __restrict__ C) {
    __shared__ __half As[ASZ];
    __shared__ __half Bs[BSZ];

    int tid = threadIdx.x;
    int wid = tid >> 5, lane = tid & 31;
    int wm = wid & 3;          // rows wm*32..+31
    int wn = wid >> 2;         // cols wn*48..+47
    int g  = lane >> 2;
    int tg = lane & 3;

    int m0  = blockIdx.x * 128;
    int b   = m0 >> 10;
    int pr0 = (m0 >> 6) & 15;

    uint32_t sA_u = smem_u32(As);
    uint32_t sB_u = smem_u32(Bs);

    // distortion coefficients + radius-poly denominator (once)
    const float* dp = dist + b*4;
    float c0 = 0.2f + dp[0], c1 = 0.2f + dp[1];
    float c2 = 0.2f + dp[2], c3 = 0.2f + dp[3];
    const float tm  = PI_F * 0.5f;
    float tm2 = tm*tm;
    float pd  = tm * (c0 + tm2*(c1 + tm2*(c2 + tm2*c3)));
    float rscl = (IMGW * 0.5f) / pd;

    // this thread's 4 azimuths (fixed across all K-tiles): precompute dirs
    int ia0 = 4 * tid;               // 0..1020
    const float SCL = 111.5f / 112.0f;
    float sy[4], cx[4];
#pragma unroll
    for (int s = 0; s < 4; s++) {
        float phi = 2.0f*PI_F * (ia0 + s + 0.5f) * (1.0f/1024.0f);
        float sp, cp;
        __sincosf(phi, &sp, &cp);
        sy[s] = sp * SCL;            // gx direction
        cx[s] = cp * SCL;            // gy direction
    }
    int pa  = ia0 >> 4;              // patch azimuth (row within half-tile)
    int aa0 = ia0 & 15;              // local azimuth within patch (0,4,8,12)
    const uint4* xb = xv + (size_t)b*HPIX;

    // ldmatrix per-thread base offsets (bytes)
    uint32_t aoff[2];
#pragma unroll
    for (int mt = 0; mt < 2; mt++) {
        int row  = wm*32 + mt*16 + (lane & 15);
        int koff = (lane >> 4) << 3;
        aoff[mt] = (uint32_t)(row*PADH + koff) * 2;
    }
    uint32_t boff[3];
#pragma unroll
    for (int p = 0; p < 3; p++) {
        int n    = wn*48 + p*16 + (lane & 7) + ((lane >> 4) << 3);
        int koff = ((lane >> 3) & 1) << 3;
        boff[p]  = (uint32_t)(n*PADH + koff) * 2;
    }

    float acc[2][6][4];
#pragma unroll
    for (int mt = 0; mt < 2; mt++)
#pragma unroll
        for (int nt = 0; nt < 6; nt++)
#pragma unroll
            for (int q = 0; q < 4; q++) acc[mt][nt][q] = 0.f;

    for (int kt = 0; kt < NKT; ++kt) {
        // ---- issue B slice (96 x 48 halves = 576 16B-chunks) ----
#pragma unroll
        for (int i = 0; i < 3; i++) {
            int e = i*256 + tid;
            if (e < 576) {
                int row = e / 6, c6 = e - row*6;
                cp16(sB_u + (uint32_t)(row*PADH + c6*8)*2,
                     Bw + (size_t)row*KDIM + kt*48 + c6*8);
            }
        }
        CP_COMMIT();

        // ---- sample 2 rings (pr0, pr0+1) at radius row kt ----
#pragma unroll
        for (int ring = 0; ring < 2; ring++) {
            int ir = (pr0 + ring)*25 + kt;
            float th = tm * (ir + 0.5f) * (1.0f/400.0f);
            float t2 = th*th;
            float rad = th * (c0 + t2*(c1 + t2*(c2 + t2*c3))) * rscl;

            uint4 qa[4], qb[4];
            float wgt[4][4];
            const uint4* base[4];
#pragma unroll
            for (int s = 0; s < 4; s++) {
                float gx = fmaf(rad, sy[s], 111.5f);
                float gy = fmaf(rad, cx[s], 111.5f);
                float x0f = floorf(gx), y0f = floorf(gy);
                float wx1 = gx - x0f, wx0 = 1.0f - wx1;
                float wy1 = gy - y0f, wy0 = 1.0f - wy1;
                int x0 = min(222, max(0, (int)x0f));
                int y0 = min(222, max(0, (int)y0f));
                wgt[s][0] = wx0*wy0; wgt[s][1] = wx1*wy0;
                wgt[s][2] = wx0*wy1; wgt[s][3] = wx1*wy1;
                base[s] = xb + y0*IMGW + x0;
            }
#pragma unroll
            for (int s = 0; s < 4; s++) {
                qa[s] = __ldg(base[s]);
                qb[s] = __ldg(base[s] + 1);
            }

            __half h[12];
#pragma unroll
            for (int s = 0; s < 4; s++) {
                float2 p00a = __half22float2(*reinterpret_cast<__half2*>(&qa[s].x));
                float2 p00b = __half22float2(*reinterpret_cast<__half2*>(&qa[s].y));
                float2 p01a = __half22float2(*reinterpret_cast<__half2*>(&qa[s].z));
                float2 p01b = __half22float2(*reinterpret_cast<__half2*>(&qa[s].w));
                float2 p10a = __half22float2(*reinterpret_cast<__half2*>(&qb[s].x));
                float2 p10b = __half22float2(*reinterpret_cast<__half2*>(&qb[s].y));
                float2 p11a = __half22float2(*reinterpret_cast<__half2*>(&qb[s].z));
                float2 p11b = __half22float2(*reinterpret_cast<__half2*>(&qb[s].w));
                float w00 = wgt[s][0], w01 = wgt[s][1], w10 = wgt[s][2], w11 = wgt[s][3];
                h[s*3+0] = __float2half_rn(w00*p00a.x + w01*p10a.x + w10*p01a.x + w11*p11a.x);
                h[s*3+1] = __float2half_rn(w00*p00a.y + w01*p10a.y + w10*p01a.y + w11*p11a.y);
                h[s*3+2] = __float2half_rn(w00*p00b.x + w01*p10b.x + w10*p01b.x + w11*p11b.x);
            }

            // write 12 consecutive halves: row = ring*64 + pa, col = 3*aa0
            __half* p = &As[(ring*64 + pa)*PADH + 3*aa0];
            uint2 u0, u1, u2;
            __half2 t01 = __halves2half2(h[0], h[1]);
            __half2 t23 = __halves2half2(h[2], h[3]);
            __half2 t45 = __halves2half2(h[4], h[5]);
            __half2 t67 = __halves2half2(h[6], h[7]);
            __half2 t89 = __halves2half2(h[8], h[9]);
            __half2 tab = __halves2half2(h[10], h[11]);
            u0.x = *reinterpret_cast<uint32_t*>(&t01);
            u0.y = *reinterpret_cast<uint32_t*>(&t23);
            u1.x = *reinterpret_cast<uint32_t*>(&t45);
            u1.y = *reinterpret_cast<uint32_t*>(&t67);
            u2.x = *reinterpret_cast<uint32_t*>(&t89);
            u2.y = *reinterpret_cast<uint32_t*>(&tab);
            *reinterpret_cast<uint2*>(p)     = u0;
            *reinterpret_cast<uint2*>(p + 4) = u1;
            *reinterpret_cast<uint2*>(p + 8) = u2;
        }

        CP_WAIT(0);
        __syncthreads();      // A sampled + B landed

        // ---- MMA: 3 k16 steps over the 48-col tile ----
#pragma unroll
        for (int ks = 0; ks < 3; ks++) {
            uint32_t kb2 = (uint32_t)ks * 32;
            uint32_t af[2][4];
#pragma unroll
            for (int mt = 0; mt < 2; mt++)
                LDSM_X4(af[mt][0], af[mt][1], af[mt][2], af[mt][3],
                        sA_u + aoff[mt] + kb2);
            uint32_t bf[6][2];
#pragma unroll
            for (int p = 0; p < 3; p++)
                LDSM_X4(bf[2*p][0], bf[2*p][1], bf[2*p+1][0], bf[2*p+1][1],
                        sB_u + boff[p] + kb2);
#pragma unroll
            for (int mt = 0; mt < 2; mt++)
#pragma unroll
                for (int nt = 0; nt < 6; nt++)
                    mma_f16(acc[mt][nt], af[mt][0], af[mt][1], af[mt][2], af[mt][3],
                            bf[nt][0], bf[nt][1]);
        }
        __syncthreads();      // MMA done before next tile overwrites As/Bs
    }

    // epilogue
#pragma unroll
    for (int nt = 0; nt < 6; nt++) {
        int col = wn*48 + nt*8 + 2*tg;
        float2 bv = *(const float2*)(bias + col);
#pragma unroll
        for (int mt = 0; mt < 2; mt++) {
            int row = m0 + wm*32 + mt*16 + g;
            float2 v0 = { acc[mt][nt][0] + bv.x, acc[mt][nt][1] + bv.y };
            float2 v1 = { acc[mt][nt][2] + bv.x, acc[mt][nt][3] + bv.y };
            *(float2*)(C + (size_t)row*96 + col)       = v0;
            *(float2*)(C + (size_t)(row + 8)*96 + col) = v1;
        }
    }
}

// ---------------------------------------------------------------------------
// Launch
// ---------------------------------------------------------------------------
extern "C" void kernel_launch(void* const* d_in, const int* in_sizes, int n_in,
                              void* d_out, int out_size) {
    const float* x    = (const float*)d_in[0];
    const float* dist = (const float*)d_in[1];
    const float* w1   = (const float*)d_in[2];
    const float* b1   = (const float*)d_in[3];
    const float* w2   = (const float*)d_in[4];
    const float* b2   = (const float*)d_in[5];
    float* out = (float*)d_out;

    __half* dWt;
    uint4* dXv;
    float* dBeff;
    cudaGetSymbolAddress((void**)&dXv,   g_xv);
    cudaGetSymbolAddress((void**)&dWt,   g_Wt);
    cudaGetSymbolAddress((void**)&dBeff, g_beff);

    int nT = MDIM * ED;
    int nTheta = (out_size > nT) ? (out_size - nT) : 0;

    prep_repack<<<NFOLD + NRB4, 256>>>(x, w1, w2, b1, b2, dXv, dWt, dBeff,
                                       out + nT, nTheta);
    fused_gemm<<<MDIM/128, 256>>>(dXv, dist, dWt, dBeff, out);
}

// round 17
// speedup vs baseline: 1.2511x; 1.2511x over previous
#include <cuda_runtime.h>
#include <cuda_fp16.h>
#include <cstdint>

// ---------------------------------------------------------------------------
// Problem constants
// ---------------------------------------------------------------------------
#define NB    32
#define IMGW  224
#define HPIX  (IMGW*IMGW)
#define ED    96
#define KDIM  1200               // 3 * 25 * 16 folded patch size
#define KPAD  1216               // padded (zero tail)
#define BK    64                 // K-tile
#define NKT   (KPAD/BK)          // 19 K-tiles
#define MDIM  (NB*16*64)         // 32768 output patches
#define PI_F  3.14159265358979323846f
#define PADH  72                 // smem row pitch in halves (64+8) -> conflict-free
#define STAGES 3

#define NSLICE 5                 // fold k-slices per c2 (5*256 >= KPAD)
#define NFOLD  (96*NSLICE)       // fold blocks = 480
#define NG4    (NB*HPIX/4)       // 4-pixel repack groups = 401408
#define NRB4   (NG4/256)         // repack blocks = 1568

// Scratch (device globals)
__device__ __half g_S[(size_t)MDIM * KPAD];   // sampled fp16, patch-major [M][KPAD]
__device__ uint4  g_xv[(size_t)NB * HPIX];    // vertical-pair packed image
__device__ __half g_Wt[(size_t)ED * KPAD];    // folded weight transposed [c2][KPAD]
__device__ float  g_beff[ED];                 // folded bias (fp32)

// ---------------------------------------------------------------------------
// PTX helpers
// ---------------------------------------------------------------------------
__device__ __forceinline__ void mma_f16(float* c, uint32_t a0, uint32_t a1,
                                        uint32_t a2, uint32_t a3,
                                        uint32_t b0, uint32_t b1) {
    asm volatile(
        "mma.sync.aligned.m16n8k16.row.col.f32.f16.f16.f32 "
        "{%0,%1,%2,%3}, {%4,%5,%6,%7}, {%8,%9}, {%0,%1,%2,%3};"
        : "+f"(c[0]), "+f"(c[1]), "+f"(c[2]), "+f"(c[3])
        : "r"(a0), "r"(a1), "r"(a2), "r"(a3), "r"(b0), "r"(b1));
}
__device__ __forceinline__ uint32_t smem_u32(const void* p) {
    uint32_t a;
    asm("{ .reg .u64 t; cvta.to.shared.u64 t, %1; cvt.u32.u64 %0, t; }" : "=r"(a) : "l"(p));
    return a;
}
__device__ __forceinline__ void cp16_ca(uint32_t dst, const void* src) {
    asm volatile("cp.async.ca.shared.global [%0], [%1], 16;" :: "r"(dst), "l"(src));
}
__device__ __forceinline__ void cp16_cg(uint32_t dst, const void* src) {
    asm volatile("cp.async.cg.shared.global [%0], [%1], 16;" :: "r"(dst), "l"(src));
}
#define CP_COMMIT()  asm volatile("cp.async.commit_group;" ::: "memory")
#define CP_WAIT(n)   asm volatile("cp.async.wait_group %0;" :: "n"(n) : "memory")
#define LDSM_X4(r0, r1, r2, r3, addr)                                             \
    asm volatile("ldmatrix.sync.aligned.m8n8.x4.shared.b16 {%0,%1,%2,%3}, [%4];"  \
        : "=r"(r0), "=r"(r1), "=r"(r2), "=r"(r3) : "r"(addr))

// ---------------------------------------------------------------------------
// Merged prep + repack (one launch).
// Blocks [0, NFOLD): weight fold, c2 = blk/NSLICE, k-slice = blk%NSLICE.
// Blocks [NFOLD, NFOLD+NRB4): 4-pixel vectorized repack + zero S tail.
// ---------------------------------------------------------------------------
__global__ __launch_bounds__(256)
void prep_repack(const float* __restrict__ x,
                 const float* __restrict__ w1, const float* __restrict__ w2,
                 const float* __restrict__ b1, const float* __restrict__ b2,
                 uint4* __restrict__ xv, __half* __restrict__ S,
                 __half* __restrict__ Wt, float* __restrict__ beff,
                 float* __restrict__ outTheta, int nTheta) {
    __shared__ float sw2[96*20];
    __shared__ float sw1[96*60];
    __shared__ float red[96];
    int t = threadIdx.x;

    if (blockIdx.x >= NFOLD) {
        // ---- vectorized repack: 4 consecutive pixels (224 % 4 == 0, same row) ----
        int g = (blockIdx.x - NFOLD) * 256 + t;     // group index, < NG4
        int b   = g / (HPIX/4);
        int rem = g - b*(HPIX/4);
        int p   = rem * 4;
        int y   = p / IMGW;
        const float* xb = x + (size_t)b*3*HPIX + p;

        float4 f0 = *(const float4*)(xb);
        float4 f1 = *(const float4*)(xb + HPIX);
        float4 f2 = *(const float4*)(xb + 2*HPIX);
        float4 e0 = {0,0,0,0}, e1 = {0,0,0,0}, e2 = {0,0,0,0};
        if (y < IMGW - 1) {
            e0 = *(const float4*)(xb + IMGW);
            e1 = *(const float4*)(xb + HPIX + IMGW);
            e2 = *(const float4*)(xb + 2*HPIX + IMGW);
        }

        uint4* dst = xv + (size_t)b*HPIX + p;
        const float* a0 = &f0.x; const float* a1 = &f1.x; const float* a2 = &f2.x;
        const float* d0 = &e0.x; const float* d1 = &e1.x; const float* d2 = &e2.x;
#pragma unroll
        for (int i = 0; i < 4; i++) {
            __half2 h0 = __floats2half2_rn(a0[i], a1[i]);
            __half2 h1 = __floats2half2_rn(a2[i], 0.f);
            __half2 h2 = __floats2half2_rn(d0[i], d1[i]);
            __half2 h3 = __floats2half2_rn(d2[i], 0.f);
            uint4 v;
            v.x = *reinterpret_cast<uint32_t*>(&h0);
            v.y = *reinterpret_cast<uint32_t*>(&h1);
            v.z = *reinterpret_cast<uint32_t*>(&h2);
            v.w = *reinterpret_cast<uint32_t*>(&h3);
            dst[i] = v;
        }

        if (g < MDIM*8) {     // zero S cols 1200..1215 (8 uint writes per row)
            int row = g >> 3, c = g & 7;
            uint32_t* Su = reinterpret_cast<uint32_t*>(S);
            Su[((size_t)row*KPAD + 1200)/2 + c] = 0u;
        }
        return;
    }

    // ---- weight fold: c2 = blk/NSLICE, slice = blk%NSLICE, k = slice*256+t ----
    int c2    = blockIdx.x / NSLICE;
    int slice = blockIdx.x - c2*NSLICE;

    for (int i = t; i < 96*20; i += 256) sw2[i] = w2[(size_t)c2*1920 + i];
    for (int i = t; i < 96*60; i += 256) sw1[i] = w1[i];
    __syncthreads();

    int k = slice*256 + t;
    if (k < KPAD) {
        if (k >= KDIM) {
            Wt[(size_t)c2*KPAD + k] = __float2half(0.f);
        } else {
            int c   = k / 400;
            int rem = k - c*400;
            int rr = rem >> 4, aa = rem & 15;
            int i = rr / 5, p = rr - i*5;
            int j = aa >> 2, q = aa & 3;
            int o2 = i*4 + j;
            int o1 = c*20 + p*4 + q;
            float s = 0.f;
#pragma unroll 8
            for (int c1 = 0; c1 < 96; c1++)
                s += sw2[c1*20 + o2] * sw1[c1*60 + o1];
            Wt[(size_t)c2*KPAD + k] = __float2half_rn(s);
        }
    }

    if (slice == 0) {
        if (t < 96) {
            float s = 0.f;
#pragma unroll
            for (int e = 0; e < 20; e++) s += sw2[t*20 + e];
            red[t] = s * b1[t];
        }
        __syncthreads();
        if (t == 0) {
            float s = b2[c2];
#pragma unroll 8
            for (int i = 0; i < 96; i++) s += red[i];
            beff[c2] = s;
        }
        if (c2 == 0 && t < nTheta) outTheta[t] = 1.5707963267948966f;   // pi/2
    }
}

// ---------------------------------------------------------------------------
// Sampling: one thread = FOUR adjacent azimuths at one radius.
// 8 independent LDG.128 (vertical pairs) + 3 STG.64. -> S fp16 [M][KPAD]
// ---------------------------------------------------------------------------
__global__ __launch_bounds__(256)
void sample_kernel(const uint4* __restrict__ xv, const float* __restrict__ dist,
                   __half* __restrict__ S) {
    int t = blockIdx.x * blockDim.x + threadIdx.x;   // 32*400*256 threads
    int j  = t & 255;                // azimuth quad index
    int ir = (t >> 8) % 400;
    int b  = t / (400*256);
    int ia0 = 4*j;

    const float* dp = dist + b*4;
    float c0 = 0.2f + dp[0], c1 = 0.2f + dp[1];
    float c2 = 0.2f + dp[2], c3 = 0.2f + dp[3];

    const float tm = PI_F * 0.5f;
    float th  = tm * (ir + 0.5f) * (1.0f/400.0f);
    float t2  = th*th;
    float pn  = th * (c0 + t2*(c1 + t2*(c2 + t2*c3)));
    float tm2 = tm*tm;
    float pd  = tm * (c0 + tm2*(c1 + tm2*(c2 + tm2*c3)));
    float r   = pn / pd * (IMGW * 0.5f);

    const uint4* xb = xv + (size_t)b*HPIX;

    uint4 qa[4], qb[4];
    float wgt[4][4];
    const uint4* base[4];
#pragma unroll
    for (int s = 0; s < 4; s++) {
        int ia = ia0 + s;
        float phi = 2.0f*PI_F * (ia + 0.5f) * (1.0f/1024.0f);
        float sp, cp;
        __sincosf(phi, &sp, &cp);
        float xc = r*cp, yc = r*sp;

        float gx = (yc * (1.0f/112.0f) + 1.0f) * 0.5f * (IMGW - 1);
        float gy = (xc * (1.0f/112.0f) + 1.0f) * 0.5f * (IMGW - 1);

        float x0f = floorf(gx), y0f = floorf(gy);
        float wx1 = gx - x0f, wx0 = 1.0f - wx1;
        float wy1 = gy - y0f, wy0 = 1.0f - wy1;
        int x0 = min(222, max(0, (int)x0f));
        int y0 = min(222, max(0, (int)y0f));

        wgt[s][0] = wx0*wy0; wgt[s][1] = wx1*wy0;
        wgt[s][2] = wx0*wy1; wgt[s][3] = wx1*wy1;
        base[s] = xb + y0*IMGW + x0;
    }
#pragma unroll
    for (int s = 0; s < 4; s++) {
        qa[s] = __ldg(base[s]);        // col x0: rows y0 (xy), y0+1 (zw)
        qb[s] = __ldg(base[s] + 1);    // col x0+1
    }

    float v[4][3];
#pragma unroll
    for (int s = 0; s < 4; s++) {
        float2 p00a = __half22float2(*reinterpret_cast<__half2*>(&qa[s].x));
        float2 p00b = __half22float2(*reinterpret_cast<__half2*>(&qa[s].y));
        float2 p01a = __half22float2(*reinterpret_cast<__half2*>(&qa[s].z));
        float2 p01b = __half22float2(*reinterpret_cast<__half2*>(&qa[s].w));
        float2 p10a = __half22float2(*reinterpret_cast<__half2*>(&qb[s].x));
        float2 p10b = __half22float2(*reinterpret_cast<__half2*>(&qb[s].y));
        float2 p11a = __half22float2(*reinterpret_cast<__half2*>(&qb[s].z));
        float2 p11b = __half22float2(*reinterpret_cast<__half2*>(&qb[s].w));
        float w00 = wgt[s][0], w01 = wgt[s][1], w10 = wgt[s][2], w11 = wgt[s][3];
        v[s][0] = w00*p00a.x + w01*p10a.x + w10*p01a.x + w11*p11a.x;
        v[s][1] = w00*p00a.y + w01*p10a.y + w10*p01a.y + w11*p11a.y;
        v[s][2] = w00*p00b.x + w01*p10b.x + w10*p01b.x + w11*p11b.x;
    }

    int patch = b*1024 + (ir/25)*64 + (ia0 >> 4);
    int col   = (ir % 25)*16 + (ia0 & 15);        // multiple of 4 -> 8B aligned
    __half* so = S + (size_t)patch*KPAD + col;
#pragma unroll
    for (int ch = 0; ch < 3; ch++) {
        __half2 p0 = __floats2half2_rn(v[0][ch], v[1][ch]);
        __half2 p1 = __floats2half2_rn(v[2][ch], v[3][ch]);
        uint2 pk;
        pk.x = *reinterpret_cast<uint32_t*>(&p0);
        pk.y = *reinterpret_cast<uint32_t*>(&p1);
        *reinterpret_cast<uint2*>(so + ch*400) = pk;
    }
}

// ---------------------------------------------------------------------------
// GEMM (fp16 mma, fp32 accum): C[M][96] = S[M][KPAD] @ Wt[96][KPAD]^T + beff
// BM=128, 256 threads (8 warps: 4M x 2N), BK=64, 3-stage cp.async pipeline,
// ldmatrix fragment loads. A via cp.async.cg (L1 bypass — stream-once),
// B via cp.async.ca (L1 reuse across the 2 resident CTAs).
// ---------------------------------------------------------------------------
#define AST (128*PADH)           // halves per A stage (9216)
#define BST (96*PADH)            // halves per B stage (6912)
#define SMEM_BYTES (STAGES*(AST+BST)*2)   // 94.5 KB

__global__ __launch_bounds__(256, 2)
void gemm_f16(const __half* __restrict__ A, const __half* __restrict__ Bw,
              const float* __restrict__ bias, float* __restrict__ C) {
    extern __shared__ __half dsm[];
    __half* As = dsm;                 // [STAGES][128][PADH]
    __half* Bs = dsm + STAGES*AST;    // [STAGES][96][PADH]

    int tid = threadIdx.x;
    int wid = tid >> 5, lane = tid & 31;
    int wm = wid & 3;          // rows wm*32..+31
    int wn = wid >> 2;         // cols wn*48..+47
    int g  = lane >> 2;
    int tg = lane & 3;

    int m0 = blockIdx.x * 128;
    const __half* Ag = A + (size_t)m0 * KPAD;

    uint32_t sA_u = smem_u32(As);
    uint32_t sB_u = smem_u32(Bs);

    uint32_t aoff[2];
#pragma unroll
    for (int mt = 0; mt < 2; mt++) {
        int row  = wm*32 + mt*16 + (lane & 15);
        int koff = (lane >> 4) << 3;
        aoff[mt] = (uint32_t)(row*PADH + koff) * 2;
    }
    uint32_t boff[3];
#pragma unroll
    for (int p = 0; p < 3; p++) {
        int n    = wn*48 + p*16 + (lane & 7) + ((lane >> 4) << 3);
        int koff = ((lane >> 3) & 1) << 3;
        boff[p]  = (uint32_t)(n*PADH + koff) * 2;
    }

    auto issue = [&](int kt, int s) {
        uint32_t abase = sA_u + (uint32_t)s*AST*2;
        uint32_t bbase = sB_u + (uint32_t)s*BST*2;
#pragma unroll
        for (int i = 0; i < 4; i++) {
            int e = i*256 + tid, row = e >> 3, c16 = e & 7;
            cp16_cg(abase + (row*PADH + c16*8)*2,
                    Ag + (size_t)row*KPAD + kt*64 + c16*8);
        }
#pragma unroll
        for (int i = 0; i < 3; i++) {
            int e = i*256 + tid, row = e >> 3, c16 = e & 7;
            cp16_ca(bbase + (row*PADH + c16*8)*2,
                    Bw + (size_t)row*KPAD + kt*64 + c16*8);
        }
    };

    float acc[2][6][4];
#pragma unroll
    for (int mt = 0; mt < 2; mt++)
#pragma unroll
        for (int nt = 0; nt < 6; nt++)
#pragma unroll
            for (int q = 0; q < 4; q++) acc[mt][nt][q] = 0.f;

#pragma unroll
    for (int s = 0; s < STAGES-1; s++) { issue(s, s); CP_COMMIT(); }

    int stage = 0;
    for (int kt = 0; kt < NKT; ++kt) {
        CP_WAIT(STAGES-2);
        __syncthreads();

        int nkt = kt + STAGES - 1;
        int nstage = stage + STAGES - 1; if (nstage >= STAGES) nstage -= STAGES;
        if (nkt < NKT) issue(nkt, nstage);
        CP_COMMIT();

        uint32_t abase = sA_u + (uint32_t)stage*AST*2;
        uint32_t bbase = sB_u + (uint32_t)stage*BST*2;

#pragma unroll
        for (int ks = 0; ks < 4; ks++) {         // four k16 steps
            uint32_t kb2 = (uint32_t)ks * 32;    // 16 halves = 32 bytes
            uint32_t af[2][4];
#pragma unroll
            for (int mt = 0; mt < 2; mt++)
                LDSM_X4(af[mt][0], af[mt][1], af[mt][2], af[mt][3],
                        abase + aoff[mt] + kb2);
            uint32_t bf[6][2];
#pragma unroll
            for (int p = 0; p < 3; p++)
                LDSM_X4(bf[2*p][0], bf[2*p][1], bf[2*p+1][0], bf[2*p+1][1],
                        bbase + boff[p] + kb2);
#pragma unroll
            for (int mt = 0; mt < 2; mt++)
#pragma unroll
                for (int nt = 0; nt < 6; nt++)
                    mma_f16(acc[mt][nt], af[mt][0], af[mt][1], af[mt][2], af[mt][3],
                            bf[nt][0], bf[nt][1]);
        }
        if (++stage == STAGES) stage = 0;
    }

    // epilogue
#pragma unroll
    for (int nt = 0; nt < 6; nt++) {
        int col = wn*48 + nt*8 + 2*tg;
        float2 bv = *(const float2*)(bias + col);
#pragma unroll
        for (int mt = 0; mt < 2; mt++) {
            int row = m0 + wm*32 + mt*16 + g;
            float2 v0 = { acc[mt][nt][0] + bv.x, acc[mt][nt][1] + bv.y };
            float2 v1 = { acc[mt][nt][2] + bv.x, acc[mt][nt][3] + bv.y };
            *(float2*)(C + (size_t)row*96 + col)       = v0;
            *(float2*)(C + (size_t)(row + 8)*96 + col) = v1;
        }
    }
}

// ---------------------------------------------------------------------------
// Launch (serial single-stream)
// ---------------------------------------------------------------------------
extern "C" void kernel_launch(void* const* d_in, const int* in_sizes, int n_in,
                              void* d_out, int out_size) {
    const float* x    = (const float*)d_in[0];
    const float* dist = (const float*)d_in[1];
    const float* w1   = (const float*)d_in[2];
    const float* b1   = (const float*)d_in[3];
    const float* w2   = (const float*)d_in[4];
    const float* b2   = (const float*)d_in[5];
    float* out = (float*)d_out;

    __half *dS, *dWt;
    uint4* dXv;
    float* dBeff;
    cudaGetSymbolAddress((void**)&dS,    g_S);
    cudaGetSymbolAddress((void**)&dXv,   g_xv);
    cudaGetSymbolAddress((void**)&dWt,   g_Wt);
    cudaGetSymbolAddress((void**)&dBeff, g_beff);

    static bool attr_done = false;
    if (!attr_done) {
        cudaFuncSetAttribute(gemm_f16, cudaFuncAttributeMaxDynamicSharedMemorySize,
                             SMEM_BYTES);
        attr_done = true;
    }

    int nT = MDIM * ED;
    int nTheta = (out_size > nT) ? (out_size - nT) : 0;

    prep_repack<<<NFOLD + NRB4, 256>>>(x, w1, w2, b1, b2, dXv, dS, dWt, dBeff,
                                       out + nT, nTheta);
    sample_kernel<<<(NB*400*256)/256, 256>>>(dXv, dist, dS);
    gemm_f16<<<MDIM/128, 256, SMEM_BYTES>>>(dS, dWt, dBeff, out);
}